// round 8
// baseline (speedup 1.0000x reference)
#include <cuda_runtime.h>

#define N_ENT   100000
#define N_EDGE  1600000
#define N_REL   64
#define N_SLOT  (N_EDGE + 8 * N_ENT)     // 2,400,000: worst-case padded size
#define NB_SCAN ((N_ENT + 255) / 256)    // 391

// Scratch (allocation-free rule: __device__ globals)
static __device__ float g_tailproj[N_ENT * 64];    // W_t · emb[n]
static __device__ float g_headrec [N_ENT * 128];   // [W_h·emb | M_h·emb]
static __device__ float g_self    [N_ENT * 128];   // [W_r·self_rel + b | M_r·self_rel]
static __device__ float g_selfrel [N_ENT * 32];    // mean incoming rel embedding
static __device__ float g_relcat  [N_REL * 128];   // [W_r·emb_rel + b | M_r·emb_rel]
static __device__ int   g_deg     [N_ENT];         // in-degree (excl. self)
static __device__ int   g_off     [N_ENT + 1];     // padded CSR offsets (mult of 8)
static __device__ int   g_cursor  [N_ENT];         // scatter cursors
static __device__ int   g_bsum    [NB_SCAN];       // scan block sums
static __device__ int   g_boff    [NB_SCAN];       // scan block offsets
static __device__ int2  g_sorted  [N_SLOT];        // (head|rel<<17, tail), 8-padded runs
static __device__ float g_sum     [N_ENT * 8];     // softmax denominators (real edges)
static __device__ float g_acc     [N_ENT * 64];    // unnormalized accum (real edges)

typedef unsigned long long u64;

__device__ __forceinline__ u64 pack2(float lo, float hi) {
    u64 r;
    asm("mov.b64 %0, {%1, %2};" : "=l"(r) : "f"(lo), "f"(hi));
    return r;
}
__device__ __forceinline__ void unpack2(u64 v, float& lo, float& hi) {
    asm("mov.b64 {%0, %1}, %2;" : "=f"(lo), "=f"(hi) : "l"(v));
}
__device__ __forceinline__ u64 fma2(u64 a, u64 b, u64 c) {
    u64 d;
    asm("fma.rn.f32x2 %0, %1, %2, %3;" : "=l"(d) : "l"(a), "l"(b), "l"(c));
    return d;
}

// ---------------------------------------------------------------------------
// Per-relation table: relcat[r] = [W_r·emb_rel[r] + attn_b | M_r·emb_rel[r]]
__global__ void rel_tables_kernel(const float* __restrict__ emb_rel,
                                  const float* __restrict__ attn_W,
                                  const float* __restrict__ attn_b,
                                  const float* __restrict__ aggr_W) {
    int r = threadIdx.x;
    if (r >= N_REL) return;
    float ev[32];
#pragma unroll
    for (int k = 0; k < 32; k++) ev[k] = emb_rel[r * 32 + k];
    for (int o = 0; o < 64; o++) {
        float a = attn_b[o], m = 0.f;
#pragma unroll
        for (int k = 0; k < 32; k++) {
            a = fmaf(attn_W[o * 96 + 64 + k], ev[k], a);
            m = fmaf(aggr_W[o * 64 + 32 + k], ev[k], m);
        }
        g_relcat[r * 128 + o]      = a;
        g_relcat[r * 128 + 64 + o] = m;
    }
}

// ---------------------------------------------------------------------------
__global__ void deg_kernel(const int* __restrict__ tail) {
    int e = blockIdx.x * blockDim.x + threadIdx.x;
    if (e < N_EDGE) atomicAdd(&g_deg[tail[e]], 1);
}

// ---------------------------------------------------------------------------
// 3-phase multi-block exclusive scan over 8-PADDED degrees
__global__ void scanA_kernel() {
    __shared__ int s[256];
    int n = blockIdx.x * 256 + threadIdx.x;
    s[threadIdx.x] = (n < N_ENT) ? ((g_deg[n] + 7) & ~7) : 0;
    __syncthreads();
    for (int o = 128; o > 0; o >>= 1) {
        if (threadIdx.x < o) s[threadIdx.x] += s[threadIdx.x + o];
        __syncthreads();
    }
    if (threadIdx.x == 0) g_bsum[blockIdx.x] = s[0];
}
__global__ void scanB_kernel() {
    __shared__ int s[512];
    int tid = threadIdx.x;
    s[tid] = (tid < NB_SCAN) ? g_bsum[tid] : 0;
    __syncthreads();
    for (int d = 1; d < 512; d <<= 1) {
        int v = (tid >= d) ? s[tid - d] : 0;
        __syncthreads();
        s[tid] += v;
        __syncthreads();
    }
    if (tid < NB_SCAN) g_boff[tid] = tid ? s[tid - 1] : 0;
    if (tid == 511) g_off[N_ENT] = s[NB_SCAN - 1];
}
__global__ void scanC_kernel() {
    __shared__ int s[256];
    int n = blockIdx.x * 256 + threadIdx.x;
    int d = (n < N_ENT) ? ((g_deg[n] + 7) & ~7) : 0;
    s[threadIdx.x] = d;
    __syncthreads();
    for (int o = 1; o < 256; o <<= 1) {
        int v = (threadIdx.x >= o) ? s[threadIdx.x - o] : 0;
        __syncthreads();
        s[threadIdx.x] += v;
        __syncthreads();
    }
    if (n < N_ENT) {
        int off = g_boff[blockIdx.x] + s[threadIdx.x] - d;   // exclusive
        g_off[n]    = off;
        g_cursor[n] = off;
    }
}

// ---------------------------------------------------------------------------
__global__ void scatter_kernel(const int* __restrict__ head,
                               const int* __restrict__ tail,
                               const int* __restrict__ rel) {
    int e = blockIdx.x * blockDim.x + threadIdx.x;
    if (e >= N_EDGE) return;
    int tn = tail[e];
    int pos = atomicAdd(&g_cursor[tn], 1);
    g_sorted[pos] = make_int2(head[e] | (rel[e] << 17), tn);
}

// ---------------------------------------------------------------------------
// Mean incoming rel embedding from the sorted runs: one warp per node.
__global__ void selfrel_kernel(const float* __restrict__ emb_rel) {
    __shared__ float s_rel[N_REL * 32];   // 8KB
    for (int i = threadIdx.x; i < N_REL * 32; i += blockDim.x)
        s_rel[i] = emb_rel[i];
    __syncthreads();
    int lane = threadIdx.x & 31;
    int n = blockIdx.x * (blockDim.x >> 5) + (threadIdx.x >> 5);
    if (n >= N_ENT) return;
    int beg = g_off[n];
    int deg = g_deg[n];
    float acc = 0.f;
    for (int i = beg; i < beg + deg; i++) {
        int rr = g_sorted[i].x >> 17;          // real edges only in [beg, beg+deg)
        acc += s_rel[rr * 32 + lane];
    }
    g_selfrel[n * 32 + lane] = acc / (float)deg;
}

// ---------------------------------------------------------------------------
// Per-node projections (5 GEMVs fused): 4 nodes per warp per k-step, weights
// packed as (o=lane, o=lane+32) float2 pairs -> LDS.64 + fma.rn.f32x2.
__global__ void __launch_bounds__(256) node_proj_kernel(
        const float* __restrict__ emb_ent,
        const float* __restrict__ attn_W,
        const float* __restrict__ attn_b,
        const float* __restrict__ aggr_W) {
    __shared__ float2 s_w[5][32 * 32];
    for (int i = threadIdx.x; i < 1024; i += blockDim.x) {
        int k = i >> 5, l = i & 31;
        s_w[0][i] = make_float2(attn_W[l * 96 + k],      attn_W[(l + 32) * 96 + k]);
        s_w[1][i] = make_float2(attn_W[l * 96 + 32 + k], attn_W[(l + 32) * 96 + 32 + k]);
        s_w[2][i] = make_float2(attn_W[l * 96 + 64 + k], attn_W[(l + 32) * 96 + 64 + k]);
        s_w[3][i] = make_float2(aggr_W[l * 64 + k],      aggr_W[(l + 32) * 64 + k]);
        s_w[4][i] = make_float2(aggr_W[l * 64 + 32 + k], aggr_W[(l + 32) * 64 + 32 + k]);
    }
    __syncthreads();

    int lane = threadIdx.x & 31;
    int gw   = blockIdx.x * (blockDim.x >> 5) + (threadIdx.x >> 5);
    int GW   = gridDim.x * (blockDim.x >> 5);
    u64 bias = pack2(attn_b[lane], attn_b[32 + lane]);

    for (int base = gw * 4; base < N_ENT; base += GW * 4) {   // N_ENT % 4 == 0
        float e0 = emb_ent[(base + 0) * 32 + lane];
        float e1 = emb_ent[(base + 1) * 32 + lane];
        float e2 = emb_ent[(base + 2) * 32 + lane];
        float e3 = emb_ent[(base + 3) * 32 + lane];
        float r0 = g_selfrel[(base + 0) * 32 + lane];
        float r1 = g_selfrel[(base + 1) * 32 + lane];
        float r2 = g_selfrel[(base + 2) * 32 + lane];
        float r3 = g_selfrel[(base + 3) * 32 + lane];

        u64 A[4], B[4], C[4], M[4], D[4];
#pragma unroll
        for (int i = 0; i < 4; i++) { A[i] = 0; B[i] = 0; C[i] = bias; M[i] = 0; D[i] = 0; }

#pragma unroll
        for (int k = 0; k < 32; k++) {
            u64 w0 = *(const u64*)&s_w[0][k * 32 + lane];
            u64 w1 = *(const u64*)&s_w[1][k * 32 + lane];
            u64 w2 = *(const u64*)&s_w[2][k * 32 + lane];
            u64 w3 = *(const u64*)&s_w[3][k * 32 + lane];
            u64 w4 = *(const u64*)&s_w[4][k * 32 + lane];
            float ek[4], sk[4];
            ek[0] = __shfl_sync(0xffffffffu, e0, k);
            ek[1] = __shfl_sync(0xffffffffu, e1, k);
            ek[2] = __shfl_sync(0xffffffffu, e2, k);
            ek[3] = __shfl_sync(0xffffffffu, e3, k);
            sk[0] = __shfl_sync(0xffffffffu, r0, k);
            sk[1] = __shfl_sync(0xffffffffu, r1, k);
            sk[2] = __shfl_sync(0xffffffffu, r2, k);
            sk[3] = __shfl_sync(0xffffffffu, r3, k);
#pragma unroll
            for (int i = 0; i < 4; i++) {
                u64 ekk = pack2(ek[i], ek[i]);
                u64 skk = pack2(sk[i], sk[i]);
                A[i] = fma2(w0, ekk, A[i]);
                B[i] = fma2(w1, ekk, B[i]);
                C[i] = fma2(w2, skk, C[i]);
                M[i] = fma2(w3, ekk, M[i]);
                D[i] = fma2(w4, skk, D[i]);
            }
        }

#pragma unroll
        for (int i = 0; i < 4; i++) {
            int n = base + i;
            float lo, hi;
            unpack2(A[i], lo, hi);
            g_tailproj[n * 64 + lane]      = lo;
            g_tailproj[n * 64 + 32 + lane] = hi;
            unpack2(B[i], lo, hi);
            g_headrec[n * 128 + lane]      = lo;
            g_headrec[n * 128 + 32 + lane] = hi;
            unpack2(M[i], lo, hi);
            g_headrec[n * 128 + 64 + lane] = lo;
            g_headrec[n * 128 + 96 + lane] = hi;
            unpack2(C[i], lo, hi);
            g_self[n * 128 + lane]         = lo;
            g_self[n * 128 + 32 + lane]    = hi;
            unpack2(D[i], lo, hi);
            g_self[n * 128 + 64 + lane]    = lo;
            g_self[n * 128 + 96 + lane]    = hi;
        }
    }
}

// ---------------------------------------------------------------------------
// Branch-free edge pass: one warp per 8-slot window; padded runs guarantee
// the whole window shares one tail. Lanes 0-15 = attention dims, 16-31 =
// message dims; dummy slots (x<0) contribute exact zeros. One flush/window.
__global__ void __launch_bounds__(256) edge_kernel(const float* __restrict__ attn_vec) {
    int t    = threadIdx.x & 31;
    int tm   = t & 15;
    int gw   = (blockIdx.x * blockDim.x + threadIdx.x) >> 5;
    int base = gw * 8;

    float4 v = *(const float4*)(&attn_vec[4 * tm]);

    int2 er[8];
#pragma unroll
    for (int i = 0; i < 8; i++) er[i] = g_sorted[base + i];

    int tn = er[0].y < 0 ? 0 : er[0].y;    // window tail (er[0] real unless all-dummy)
    float4 at = *(const float4*)(&g_tailproj[tn * 64 + 4 * tm]);
    float ax = 0, ay = 0, az = 0, aw = 0, den = 0;

#pragma unroll
    for (int i = 0; i < 8; i++) {
        int x = er[i].x;
        bool valid = x >= 0;
        int hn = valid ? (x & 0x1FFFF) : 0;
        int r  = valid ? (x >> 17) : 0;

        float4 h4 = *(const float4*)(&g_headrec[hn * 128 + 4 * t]);
        float4 c4 = *(const float4*)(&g_relcat[r * 128 + 4 * t]);

        float qx = h4.x + c4.x, qy = h4.y + c4.y;
        float qz = h4.z + c4.z, qw = h4.w + c4.w;
        float p0 = at.x + qx; p0 = fmaxf(p0, 0.2f * p0);   // leaky_relu
        float p1 = at.y + qy; p1 = fmaxf(p1, 0.2f * p1);
        float p2 = at.z + qz; p2 = fmaxf(p2, 0.2f * p2);
        float p3 = at.w + qw; p3 = fmaxf(p3, 0.2f * p3);
        float s = p0 * v.x + p1 * v.y + p2 * v.z + p3 * v.w;
        s += __shfl_xor_sync(0xffffffffu, s, 1);           // per-head pair sum
        float ex = __expf(s);                              // logits O(1): no max pass
        ex = valid ? ex : 0.f;
        float exm = __shfl_sync(0xffffffffu, ex, tm);      // lanes 16-31 fetch their head

        ax = fmaf(exm, qx, ax);
        ay = fmaf(exm, qy, ay);
        az = fmaf(exm, qz, az);
        aw = fmaf(exm, qw, aw);
        den += ex;
    }

    if (t >= 16) {                          // message dims: one RED per window
        float* dst = &g_acc[tn * 64 + 4 * (t - 16)];
        asm volatile("red.global.add.v4.f32 [%0], {%1,%2,%3,%4};"
                     :: "l"(dst), "f"(ax), "f"(ay), "f"(az), "f"(aw) : "memory");
    } else if (!(t & 1)) {                  // one denominator add per head
        atomicAdd(&g_sum[tn * 8 + (t >> 1)], den);
    }
}

// ---------------------------------------------------------------------------
// Self-loop edge + normalize + bias: 16 lanes per node, 2 nodes per warp.
__global__ void final_kernel(const float* __restrict__ attn_vec,
                             const float* __restrict__ aggr_b,
                             float* __restrict__ out) {
    int lane = threadIdx.x & 31;
    int t    = lane & 15;
    int sub  = lane >> 4;
    unsigned pmask = 3u << (lane & 30);
    int gw = (blockIdx.x * blockDim.x + threadIdx.x) >> 5;
    int n  = gw * 2 + sub;                   // N_ENT % 2 == 0: exact
    if (n >= N_ENT) return;

    float4 v  = *(const float4*)(&attn_vec[4 * t]);
    float4 at = *(const float4*)(&g_tailproj[n * 64 + 4 * t]);
    float4 ah = *(const float4*)(&g_headrec[n * 128 + 4 * t]);
    float4 mh = *(const float4*)(&g_headrec[n * 128 + 64 + 4 * t]);
    float4 ar = *(const float4*)(&g_self[n * 128 + 4 * t]);
    float4 mr = *(const float4*)(&g_self[n * 128 + 64 + 4 * t]);

    float p0 = at.x + ah.x + ar.x; p0 = fmaxf(p0, 0.2f * p0);
    float p1 = at.y + ah.y + ar.y; p1 = fmaxf(p1, 0.2f * p1);
    float p2 = at.z + ah.z + ar.z; p2 = fmaxf(p2, 0.2f * p2);
    float p3 = at.w + ah.w + ar.w; p3 = fmaxf(p3, 0.2f * p3);
    float s = p0 * v.x + p1 * v.y + p2 * v.z + p3 * v.w;
    s += __shfl_xor_sync(pmask, s, 1);
    float ex = __expf(s);

    float4 acc = *(const float4*)(&g_acc[n * 64 + 4 * t]);
    float den  = g_sum[n * 8 + (t >> 1)];
    float inv  = 1.f / (den + ex + 1e-16f);
    float4 b   = *(const float4*)(&aggr_b[4 * t]);

    float4 o;
    o.x = fmaf(fmaf(ex, mh.x + mr.x, acc.x), inv, b.x);
    o.y = fmaf(fmaf(ex, mh.y + mr.y, acc.y), inv, b.y);
    o.z = fmaf(fmaf(ex, mh.z + mr.z, acc.z), inv, b.z);
    o.w = fmaf(fmaf(ex, mh.w + mr.w, acc.w), inv, b.w);
    *(float4*)(&out[n * 64 + 4 * t]) = o;
}

// ---------------------------------------------------------------------------
extern "C" void kernel_launch(void* const* d_in, const int* in_sizes, int n_in,
                              void* d_out, int out_size) {
    const float* emb_ent  = (const float*)d_in[0];
    const float* emb_rel  = (const float*)d_in[1];
    const float* attn_W   = (const float*)d_in[2];
    const float* attn_b   = (const float*)d_in[3];
    const float* attn_vec = (const float*)d_in[4];
    const float* aggr_W   = (const float*)d_in[5];
    const float* aggr_b   = (const float*)d_in[6];
    const int*   head     = (const int*)d_in[7];
    const int*   tail     = (const int*)d_in[8];
    const int*   rel      = (const int*)d_in[9];
    float*       out      = (float*)d_out;

    void *p_deg, *p_sum, *p_acc, *p_sorted;
    cudaGetSymbolAddress(&p_deg,    g_deg);
    cudaGetSymbolAddress(&p_sum,    g_sum);
    cudaGetSymbolAddress(&p_acc,    g_acc);
    cudaGetSymbolAddress(&p_sorted, g_sorted);
    cudaMemsetAsync(p_deg,    0,    sizeof(int)   * N_ENT);
    cudaMemsetAsync(p_sum,    0,    sizeof(float) * N_ENT * 8);
    cudaMemsetAsync(p_acc,    0,    sizeof(float) * N_ENT * 64);
    cudaMemsetAsync(p_sorted, 0xFF, sizeof(int2)  * N_SLOT);   // dummy = -1

    rel_tables_kernel<<<1, 64>>>(emb_rel, attn_W, attn_b, aggr_W);
    deg_kernel<<<(N_EDGE + 255) / 256, 256>>>(tail);
    scanA_kernel<<<NB_SCAN, 256>>>();
    scanB_kernel<<<1, 512>>>();
    scanC_kernel<<<NB_SCAN, 256>>>();
    scatter_kernel<<<(N_EDGE + 255) / 256, 256>>>(head, tail, rel);
    selfrel_kernel<<<(N_ENT + 7) / 8, 256>>>(emb_rel);
    node_proj_kernel<<<740, 256>>>(emb_ent, attn_W, attn_b, aggr_W);
    edge_kernel<<<N_SLOT / 8 / 8, 256>>>(attn_vec);   // warp per 8-slot window
    final_kernel<<<(N_ENT / 2 + 7) / 8, 256>>>(attn_vec, aggr_b, out);
}

// round 9
// speedup vs baseline: 1.6852x; 1.6852x over previous
#include <cuda_runtime.h>

#define N_ENT   100000
#define N_EDGE  1600000
#define N_REL   64
#define NB_SCAN ((N_ENT + 255) / 256)    // 391

// Scratch (allocation-free rule: __device__ globals)
static __device__ float g_tailproj[N_ENT * 64];    // W_t · emb[n]
static __device__ float g_headrec [N_ENT * 128];   // [W_h·emb | M_h·emb]
static __device__ float g_self    [N_ENT * 128];   // [W_r·self_rel + b | M_r·self_rel]
static __device__ float g_selfrel [N_ENT * 32];    // mean incoming rel embedding
static __device__ float g_relcat  [N_REL * 128];   // [W_r·emb_rel + b | M_r·emb_rel]
static __device__ int   g_deg     [N_ENT];         // in-degree (excl. self)
static __device__ int   g_off     [N_ENT + 1];     // CSR offsets
static __device__ int   g_cursor  [N_ENT];         // scatter cursors
static __device__ int   g_bsum    [NB_SCAN];       // scan block sums
static __device__ int   g_boff    [NB_SCAN];       // scan block offsets
static __device__ int   g_sortkey [N_EDGE];        // head | rel<<17, grouped by tail

typedef unsigned long long u64;

__device__ __forceinline__ u64 pack2(float lo, float hi) {
    u64 r;
    asm("mov.b64 %0, {%1, %2};" : "=l"(r) : "f"(lo), "f"(hi));
    return r;
}
__device__ __forceinline__ void unpack2(u64 v, float& lo, float& hi) {
    asm("mov.b64 {%0, %1}, %2;" : "=f"(lo), "=f"(hi) : "l"(v));
}
__device__ __forceinline__ u64 fma2(u64 a, u64 b, u64 c) {
    u64 d;
    asm("fma.rn.f32x2 %0, %1, %2, %3;" : "=l"(d) : "l"(a), "l"(b), "l"(c));
    return d;
}

// ---------------------------------------------------------------------------
// Per-relation table: relcat[r] = [W_r·emb_rel[r] + attn_b | M_r·emb_rel[r]]
__global__ void rel_tables_kernel(const float* __restrict__ emb_rel,
                                  const float* __restrict__ attn_W,
                                  const float* __restrict__ attn_b,
                                  const float* __restrict__ aggr_W) {
    int r = threadIdx.x;
    if (r >= N_REL) return;
    float ev[32];
#pragma unroll
    for (int k = 0; k < 32; k++) ev[k] = emb_rel[r * 32 + k];
    for (int o = 0; o < 64; o++) {
        float a = attn_b[o], m = 0.f;
#pragma unroll
        for (int k = 0; k < 32; k++) {
            a = fmaf(attn_W[o * 96 + 64 + k], ev[k], a);
            m = fmaf(aggr_W[o * 64 + 32 + k], ev[k], m);
        }
        g_relcat[r * 128 + o]      = a;
        g_relcat[r * 128 + 64 + o] = m;
    }
}

// ---------------------------------------------------------------------------
__global__ void deg_kernel(const int* __restrict__ tail) {
    int e = blockIdx.x * blockDim.x + threadIdx.x;
    if (e < N_EDGE) atomicAdd(&g_deg[tail[e]], 1);
}

// ---------------------------------------------------------------------------
// 3-phase multi-block exclusive scan over degrees
__global__ void scanA_kernel() {
    __shared__ int s[256];
    int n = blockIdx.x * 256 + threadIdx.x;
    s[threadIdx.x] = (n < N_ENT) ? g_deg[n] : 0;
    __syncthreads();
    for (int o = 128; o > 0; o >>= 1) {
        if (threadIdx.x < o) s[threadIdx.x] += s[threadIdx.x + o];
        __syncthreads();
    }
    if (threadIdx.x == 0) g_bsum[blockIdx.x] = s[0];
}
__global__ void scanB_kernel() {
    __shared__ int s[512];
    int tid = threadIdx.x;
    s[tid] = (tid < NB_SCAN) ? g_bsum[tid] : 0;
    __syncthreads();
    for (int d = 1; d < 512; d <<= 1) {
        int v = (tid >= d) ? s[tid - d] : 0;
        __syncthreads();
        s[tid] += v;
        __syncthreads();
    }
    if (tid < NB_SCAN) g_boff[tid] = tid ? s[tid - 1] : 0;
    if (tid == 511) g_off[N_ENT] = s[NB_SCAN - 1];
}
__global__ void scanC_kernel() {
    __shared__ int s[256];
    int n = blockIdx.x * 256 + threadIdx.x;
    int d = (n < N_ENT) ? g_deg[n] : 0;
    s[threadIdx.x] = d;
    __syncthreads();
    for (int o = 1; o < 256; o <<= 1) {
        int v = (threadIdx.x >= o) ? s[threadIdx.x - o] : 0;
        __syncthreads();
        s[threadIdx.x] += v;
        __syncthreads();
    }
    if (n < N_ENT) {
        int off = g_boff[blockIdx.x] + s[threadIdx.x] - d;   // exclusive
        g_off[n]    = off;
        g_cursor[n] = off;
    }
}

// ---------------------------------------------------------------------------
__global__ void scatter_kernel(const int* __restrict__ head,
                               const int* __restrict__ tail,
                               const int* __restrict__ rel) {
    int e = blockIdx.x * blockDim.x + threadIdx.x;
    if (e >= N_EDGE) return;
    int pos = atomicAdd(&g_cursor[tail[e]], 1);
    g_sortkey[pos] = head[e] | (rel[e] << 17);
}

// ---------------------------------------------------------------------------
// Mean incoming rel embedding from the sorted runs: one warp per node.
__global__ void selfrel_kernel(const float* __restrict__ emb_rel) {
    __shared__ float s_rel[N_REL * 32];   // 8KB
    for (int i = threadIdx.x; i < N_REL * 32; i += blockDim.x)
        s_rel[i] = emb_rel[i];
    __syncthreads();
    int lane = threadIdx.x & 31;
    int n = blockIdx.x * (blockDim.x >> 5) + (threadIdx.x >> 5);
    if (n >= N_ENT) return;
    int beg = g_off[n], end = g_off[n + 1];
    float acc = 0.f;
    for (int i = beg; i < end; i++) {
        int rr = g_sortkey[i] >> 17;
        acc += s_rel[rr * 32 + lane];
    }
    g_selfrel[n * 32 + lane] = acc / (float)(end - beg);
}

// ---------------------------------------------------------------------------
// Per-node projections (5 GEMVs fused): 4 nodes per warp per k-step, weights
// packed as (o=lane, o=lane+32) float2 pairs -> LDS.64 + fma.rn.f32x2.
__global__ void __launch_bounds__(256) node_proj_kernel(
        const float* __restrict__ emb_ent,
        const float* __restrict__ attn_W,
        const float* __restrict__ attn_b,
        const float* __restrict__ aggr_W) {
    __shared__ float2 s_w[5][32 * 32];
    for (int i = threadIdx.x; i < 1024; i += blockDim.x) {
        int k = i >> 5, l = i & 31;
        s_w[0][i] = make_float2(attn_W[l * 96 + k],      attn_W[(l + 32) * 96 + k]);
        s_w[1][i] = make_float2(attn_W[l * 96 + 32 + k], attn_W[(l + 32) * 96 + 32 + k]);
        s_w[2][i] = make_float2(attn_W[l * 96 + 64 + k], attn_W[(l + 32) * 96 + 64 + k]);
        s_w[3][i] = make_float2(aggr_W[l * 64 + k],      aggr_W[(l + 32) * 64 + k]);
        s_w[4][i] = make_float2(aggr_W[l * 64 + 32 + k], aggr_W[(l + 32) * 64 + 32 + k]);
    }
    __syncthreads();

    int lane = threadIdx.x & 31;
    int gw   = blockIdx.x * (blockDim.x >> 5) + (threadIdx.x >> 5);
    int GW   = gridDim.x * (blockDim.x >> 5);
    u64 bias = pack2(attn_b[lane], attn_b[32 + lane]);

    for (int base = gw * 4; base < N_ENT; base += GW * 4) {   // N_ENT % 4 == 0
        float e0 = emb_ent[(base + 0) * 32 + lane];
        float e1 = emb_ent[(base + 1) * 32 + lane];
        float e2 = emb_ent[(base + 2) * 32 + lane];
        float e3 = emb_ent[(base + 3) * 32 + lane];
        float r0 = g_selfrel[(base + 0) * 32 + lane];
        float r1 = g_selfrel[(base + 1) * 32 + lane];
        float r2 = g_selfrel[(base + 2) * 32 + lane];
        float r3 = g_selfrel[(base + 3) * 32 + lane];

        u64 A[4], B[4], C[4], M[4], D[4];
#pragma unroll
        for (int i = 0; i < 4; i++) { A[i] = 0; B[i] = 0; C[i] = bias; M[i] = 0; D[i] = 0; }

#pragma unroll
        for (int k = 0; k < 32; k++) {
            u64 w0 = *(const u64*)&s_w[0][k * 32 + lane];
            u64 w1 = *(const u64*)&s_w[1][k * 32 + lane];
            u64 w2 = *(const u64*)&s_w[2][k * 32 + lane];
            u64 w3 = *(const u64*)&s_w[3][k * 32 + lane];
            u64 w4 = *(const u64*)&s_w[4][k * 32 + lane];
            float ek[4], sk[4];
            ek[0] = __shfl_sync(0xffffffffu, e0, k);
            ek[1] = __shfl_sync(0xffffffffu, e1, k);
            ek[2] = __shfl_sync(0xffffffffu, e2, k);
            ek[3] = __shfl_sync(0xffffffffu, e3, k);
            sk[0] = __shfl_sync(0xffffffffu, r0, k);
            sk[1] = __shfl_sync(0xffffffffu, r1, k);
            sk[2] = __shfl_sync(0xffffffffu, r2, k);
            sk[3] = __shfl_sync(0xffffffffu, r3, k);
#pragma unroll
            for (int i = 0; i < 4; i++) {
                u64 ekk = pack2(ek[i], ek[i]);
                u64 skk = pack2(sk[i], sk[i]);
                A[i] = fma2(w0, ekk, A[i]);
                B[i] = fma2(w1, ekk, B[i]);
                C[i] = fma2(w2, skk, C[i]);
                M[i] = fma2(w3, ekk, M[i]);
                D[i] = fma2(w4, skk, D[i]);
            }
        }

#pragma unroll
        for (int i = 0; i < 4; i++) {
            int n = base + i;
            float lo, hi;
            unpack2(A[i], lo, hi);
            g_tailproj[n * 64 + lane]      = lo;
            g_tailproj[n * 64 + 32 + lane] = hi;
            unpack2(B[i], lo, hi);
            g_headrec[n * 128 + lane]      = lo;
            g_headrec[n * 128 + 32 + lane] = hi;
            unpack2(M[i], lo, hi);
            g_headrec[n * 128 + 64 + lane] = lo;
            g_headrec[n * 128 + 96 + lane] = hi;
            unpack2(C[i], lo, hi);
            g_self[n * 128 + lane]         = lo;
            g_self[n * 128 + 32 + lane]    = hi;
            unpack2(D[i], lo, hi);
            g_self[n * 128 + 64 + lane]    = lo;
            g_self[n * 128 + 96 + lane]    = hi;
        }
    }
}

// ---------------------------------------------------------------------------
// Fused CSR aggregate: one warp per node (grid-stride), 2 edges in flight
// (16-lane groups). Rel tables in smem. Register accumulation, direct output
// write with self-loop + softmax normalize + bias fused. Zero atomics.
__global__ void __launch_bounds__(256) aggregate_kernel(
        const float* __restrict__ attn_vec,
        const float* __restrict__ aggr_b,
        float* __restrict__ out) {
    __shared__ float4 s_rel[N_REL * 32];   // 32KB: row r = 32 float4s
    {
        const float4* src = (const float4*)g_relcat;
        for (int i = threadIdx.x; i < N_REL * 32; i += blockDim.x)
            s_rel[i] = src[i];
    }
    __syncthreads();

    int lane = threadIdx.x & 31;
    int t    = lane & 15;
    int sub  = lane >> 4;
    unsigned pmask = 3u << (lane & 30);
    int gw = blockIdx.x * (blockDim.x >> 5) + (threadIdx.x >> 5);
    int GW = gridDim.x * (blockDim.x >> 5);

    float4 v  = *(const float4*)(&attn_vec[4 * t]);
    float4 b4 = *(const float4*)(&aggr_b[4 * t]);

    for (int n = gw; n < N_ENT; n += GW) {
        int beg = g_off[n], end = g_off[n + 1];
        float4 at = *(const float4*)(&g_tailproj[n * 64 + 4 * t]);
        float ax = 0, ay = 0, az = 0, aw = 0, den = 0;

        for (int i = beg + sub; i < end; i += 2) {
            int x  = g_sortkey[i];
            int hn = x & 0x1FFFF;
            int r  = x >> 17;
            float4 ah = *(const float4*)(&g_headrec[hn * 128 + 4 * t]);
            float4 mh = *(const float4*)(&g_headrec[hn * 128 + 64 + 4 * t]);
            float4 cr = s_rel[r * 32 + t];        // attn half
            float4 mr = s_rel[r * 32 + 16 + t];   // message half

            float p0 = at.x + ah.x + cr.x; p0 = fmaxf(p0, 0.2f * p0);  // leaky
            float p1 = at.y + ah.y + cr.y; p1 = fmaxf(p1, 0.2f * p1);
            float p2 = at.z + ah.z + cr.z; p2 = fmaxf(p2, 0.2f * p2);
            float p3 = at.w + ah.w + cr.w; p3 = fmaxf(p3, 0.2f * p3);
            float s = p0 * v.x + p1 * v.y + p2 * v.z + p3 * v.w;
            s += __shfl_xor_sync(pmask, s, 1);    // per-head pair sum (sub-local)
            float ex = __expf(s);                 // logits O(1): max-pass skip safe

            ax = fmaf(ex, mh.x + mr.x, ax);
            ay = fmaf(ex, mh.y + mr.y, ay);
            az = fmaf(ex, mh.z + mr.z, az);
            aw = fmaf(ex, mh.w + mr.w, aw);
            den += ex;
        }

        // combine the two 16-lane halves (same dims, different edges)
        ax  += __shfl_xor_sync(0xffffffffu, ax, 16);
        ay  += __shfl_xor_sync(0xffffffffu, ay, 16);
        az  += __shfl_xor_sync(0xffffffffu, az, 16);
        aw  += __shfl_xor_sync(0xffffffffu, aw, 16);
        den += __shfl_xor_sync(0xffffffffu, den, 16);

        if (sub == 0) {
            // self-loop edge + normalize + bias
            float4 ahs = *(const float4*)(&g_headrec[n * 128 + 4 * t]);
            float4 mhs = *(const float4*)(&g_headrec[n * 128 + 64 + 4 * t]);
            float4 ars = *(const float4*)(&g_self[n * 128 + 4 * t]);
            float4 mrs = *(const float4*)(&g_self[n * 128 + 64 + 4 * t]);

            float p0 = at.x + ahs.x + ars.x; p0 = fmaxf(p0, 0.2f * p0);
            float p1 = at.y + ahs.y + ars.y; p1 = fmaxf(p1, 0.2f * p1);
            float p2 = at.z + ahs.z + ars.z; p2 = fmaxf(p2, 0.2f * p2);
            float p3 = at.w + ahs.w + ars.w; p3 = fmaxf(p3, 0.2f * p3);
            float s = p0 * v.x + p1 * v.y + p2 * v.z + p3 * v.w;
            s += __shfl_xor_sync(pmask, s, 1);
            float ex = __expf(s);

            float inv = 1.f / (den + ex + 1e-16f);
            float4 o;
            o.x = fmaf(fmaf(ex, mhs.x + mrs.x, ax), inv, b4.x);
            o.y = fmaf(fmaf(ex, mhs.y + mrs.y, ay), inv, b4.y);
            o.z = fmaf(fmaf(ex, mhs.z + mrs.z, az), inv, b4.z);
            o.w = fmaf(fmaf(ex, mhs.w + mrs.w, aw), inv, b4.w);
            *(float4*)(&out[n * 64 + 4 * t]) = o;
        }
    }
}

// ---------------------------------------------------------------------------
extern "C" void kernel_launch(void* const* d_in, const int* in_sizes, int n_in,
                              void* d_out, int out_size) {
    const float* emb_ent  = (const float*)d_in[0];
    const float* emb_rel  = (const float*)d_in[1];
    const float* attn_W   = (const float*)d_in[2];
    const float* attn_b   = (const float*)d_in[3];
    const float* attn_vec = (const float*)d_in[4];
    const float* aggr_W   = (const float*)d_in[5];
    const float* aggr_b   = (const float*)d_in[6];
    const int*   head     = (const int*)d_in[7];
    const int*   tail     = (const int*)d_in[8];
    const int*   rel      = (const int*)d_in[9];
    float*       out      = (float*)d_out;

    void* p_deg;
    cudaGetSymbolAddress(&p_deg, g_deg);
    cudaMemsetAsync(p_deg, 0, sizeof(int) * N_ENT);

    rel_tables_kernel<<<1, 64>>>(emb_rel, attn_W, attn_b, aggr_W);
    deg_kernel<<<(N_EDGE + 255) / 256, 256>>>(tail);
    scanA_kernel<<<NB_SCAN, 256>>>();
    scanB_kernel<<<1, 512>>>();
    scanC_kernel<<<NB_SCAN, 256>>>();
    scatter_kernel<<<(N_EDGE + 255) / 256, 256>>>(head, tail, rel);
    selfrel_kernel<<<(N_ENT + 7) / 8, 256>>>(emb_rel);
    node_proj_kernel<<<740, 256>>>(emb_ent, attn_W, attn_b, aggr_W);
    aggregate_kernel<<<592, 256>>>(attn_vec, aggr_b, out);
}

// round 10
// speedup vs baseline: 1.7002x; 1.0089x over previous
#include <cuda_runtime.h>
#include <cuda_fp16.h>

#define N_ENT   100000
#define N_EDGE  1600000
#define N_REL   64
#define NB_SCAN ((N_ENT + 255) / 256)    // 391

// Scratch (allocation-free rule: __device__ globals)
static __device__ float  g_tailproj[N_ENT * 64];   // W_t · emb[n]           (fp32)
static __device__ __half g_headrec [N_ENT * 128];  // [W_h·emb | M_h·emb]    (fp16)
static __device__ float  g_self    [N_ENT * 128];  // [W_r·self_rel+b | M_r·self_rel]
static __device__ float  g_selfrel [N_ENT * 32];   // mean incoming rel embedding
static __device__ float  g_relcat  [N_REL * 128];  // [W_r·emb_rel+b | M_r·emb_rel]
static __device__ int    g_deg     [N_ENT];        // in-degree (excl. self)
static __device__ int    g_off     [N_ENT + 1];    // CSR offsets
static __device__ int    g_cursor  [N_ENT];        // scatter cursors
static __device__ int    g_bsum    [NB_SCAN];      // scan block sums
static __device__ int    g_boff    [NB_SCAN];      // scan block offsets
static __device__ int    g_sortkey [N_EDGE];       // head | rel<<17, grouped by tail

typedef unsigned long long u64;

__device__ __forceinline__ u64 pack2(float lo, float hi) {
    u64 r;
    asm("mov.b64 %0, {%1, %2};" : "=l"(r) : "f"(lo), "f"(hi));
    return r;
}
__device__ __forceinline__ void unpack2(u64 v, float& lo, float& hi) {
    asm("mov.b64 {%0, %1}, %2;" : "=f"(lo), "=f"(hi) : "l"(v));
}
__device__ __forceinline__ u64 fma2(u64 a, u64 b, u64 c) {
    u64 d;
    asm("fma.rn.f32x2 %0, %1, %2, %3;" : "=l"(d) : "l"(a), "l"(b), "l"(c));
    return d;
}

// ---------------------------------------------------------------------------
// Per-relation table: relcat[r] = [W_r·emb_rel[r] + attn_b | M_r·emb_rel[r]]
__global__ void rel_tables_kernel(const float* __restrict__ emb_rel,
                                  const float* __restrict__ attn_W,
                                  const float* __restrict__ attn_b,
                                  const float* __restrict__ aggr_W) {
    int r = threadIdx.x;
    if (r >= N_REL) return;
    float ev[32];
#pragma unroll
    for (int k = 0; k < 32; k++) ev[k] = emb_rel[r * 32 + k];
    for (int o = 0; o < 64; o++) {
        float a = attn_b[o], m = 0.f;
#pragma unroll
        for (int k = 0; k < 32; k++) {
            a = fmaf(attn_W[o * 96 + 64 + k], ev[k], a);
            m = fmaf(aggr_W[o * 64 + 32 + k], ev[k], m);
        }
        g_relcat[r * 128 + o]      = a;
        g_relcat[r * 128 + 64 + o] = m;
    }
}

// ---------------------------------------------------------------------------
__global__ void deg_kernel(const int* __restrict__ tail) {
    int e = blockIdx.x * blockDim.x + threadIdx.x;
    if (e < N_EDGE) atomicAdd(&g_deg[tail[e]], 1);
}

// ---------------------------------------------------------------------------
// 3-phase multi-block exclusive scan over degrees
__global__ void scanA_kernel() {
    __shared__ int s[256];
    int n = blockIdx.x * 256 + threadIdx.x;
    s[threadIdx.x] = (n < N_ENT) ? g_deg[n] : 0;
    __syncthreads();
    for (int o = 128; o > 0; o >>= 1) {
        if (threadIdx.x < o) s[threadIdx.x] += s[threadIdx.x + o];
        __syncthreads();
    }
    if (threadIdx.x == 0) g_bsum[blockIdx.x] = s[0];
}
__global__ void scanB_kernel() {
    __shared__ int s[512];
    int tid = threadIdx.x;
    s[tid] = (tid < NB_SCAN) ? g_bsum[tid] : 0;
    __syncthreads();
    for (int d = 1; d < 512; d <<= 1) {
        int v = (tid >= d) ? s[tid - d] : 0;
        __syncthreads();
        s[tid] += v;
        __syncthreads();
    }
    if (tid < NB_SCAN) g_boff[tid] = tid ? s[tid - 1] : 0;
    if (tid == 511) g_off[N_ENT] = s[NB_SCAN - 1];
}
__global__ void scanC_kernel() {
    __shared__ int s[256];
    int n = blockIdx.x * 256 + threadIdx.x;
    int d = (n < N_ENT) ? g_deg[n] : 0;
    s[threadIdx.x] = d;
    __syncthreads();
    for (int o = 1; o < 256; o <<= 1) {
        int v = (threadIdx.x >= o) ? s[threadIdx.x - o] : 0;
        __syncthreads();
        s[threadIdx.x] += v;
        __syncthreads();
    }
    if (n < N_ENT) {
        int off = g_boff[blockIdx.x] + s[threadIdx.x] - d;   // exclusive
        g_off[n]    = off;
        g_cursor[n] = off;
    }
}

// ---------------------------------------------------------------------------
__global__ void scatter_kernel(const int* __restrict__ head,
                               const int* __restrict__ tail,
                               const int* __restrict__ rel) {
    int e = blockIdx.x * blockDim.x + threadIdx.x;
    if (e >= N_EDGE) return;
    int pos = atomicAdd(&g_cursor[tail[e]], 1);
    g_sortkey[pos] = head[e] | (rel[e] << 17);
}

// ---------------------------------------------------------------------------
// Mean incoming rel embedding from the sorted runs: one warp per node.
__global__ void selfrel_kernel(const float* __restrict__ emb_rel) {
    __shared__ float s_rel[N_REL * 32];   // 8KB
    for (int i = threadIdx.x; i < N_REL * 32; i += blockDim.x)
        s_rel[i] = emb_rel[i];
    __syncthreads();
    int lane = threadIdx.x & 31;
    int n = blockIdx.x * (blockDim.x >> 5) + (threadIdx.x >> 5);
    if (n >= N_ENT) return;
    int beg = g_off[n], end = g_off[n + 1];
    float acc = 0.f;
    for (int i = beg; i < end; i++) {
        int rr = g_sortkey[i] >> 17;
        acc += s_rel[rr * 32 + lane];
    }
    g_selfrel[n * 32 + lane] = acc / (float)(end - beg);
}

// ---------------------------------------------------------------------------
// Per-node projections (5 GEMVs fused): 4 nodes per warp per k-step, weights
// packed as (o=lane, o=lane+32) float2 pairs -> LDS.64 + fma.rn.f32x2.
// headrec is written in fp16 (halves the aggregate pass's gather traffic).
__global__ void __launch_bounds__(256) node_proj_kernel(
        const float* __restrict__ emb_ent,
        const float* __restrict__ attn_W,
        const float* __restrict__ attn_b,
        const float* __restrict__ aggr_W) {
    __shared__ float2 s_w[5][32 * 32];
    for (int i = threadIdx.x; i < 1024; i += blockDim.x) {
        int k = i >> 5, l = i & 31;
        s_w[0][i] = make_float2(attn_W[l * 96 + k],      attn_W[(l + 32) * 96 + k]);
        s_w[1][i] = make_float2(attn_W[l * 96 + 32 + k], attn_W[(l + 32) * 96 + 32 + k]);
        s_w[2][i] = make_float2(attn_W[l * 96 + 64 + k], attn_W[(l + 32) * 96 + 64 + k]);
        s_w[3][i] = make_float2(aggr_W[l * 64 + k],      aggr_W[(l + 32) * 64 + k]);
        s_w[4][i] = make_float2(aggr_W[l * 64 + 32 + k], aggr_W[(l + 32) * 64 + 32 + k]);
    }
    __syncthreads();

    int lane = threadIdx.x & 31;
    int gw   = blockIdx.x * (blockDim.x >> 5) + (threadIdx.x >> 5);
    int GW   = gridDim.x * (blockDim.x >> 5);
    u64 bias = pack2(attn_b[lane], attn_b[32 + lane]);

    for (int base = gw * 4; base < N_ENT; base += GW * 4) {   // N_ENT % 4 == 0
        float e0 = emb_ent[(base + 0) * 32 + lane];
        float e1 = emb_ent[(base + 1) * 32 + lane];
        float e2 = emb_ent[(base + 2) * 32 + lane];
        float e3 = emb_ent[(base + 3) * 32 + lane];
        float r0 = g_selfrel[(base + 0) * 32 + lane];
        float r1 = g_selfrel[(base + 1) * 32 + lane];
        float r2 = g_selfrel[(base + 2) * 32 + lane];
        float r3 = g_selfrel[(base + 3) * 32 + lane];

        u64 A[4], B[4], C[4], M[4], D[4];
#pragma unroll
        for (int i = 0; i < 4; i++) { A[i] = 0; B[i] = 0; C[i] = bias; M[i] = 0; D[i] = 0; }

#pragma unroll
        for (int k = 0; k < 32; k++) {
            u64 w0 = *(const u64*)&s_w[0][k * 32 + lane];
            u64 w1 = *(const u64*)&s_w[1][k * 32 + lane];
            u64 w2 = *(const u64*)&s_w[2][k * 32 + lane];
            u64 w3 = *(const u64*)&s_w[3][k * 32 + lane];
            u64 w4 = *(const u64*)&s_w[4][k * 32 + lane];
            float ek[4], sk[4];
            ek[0] = __shfl_sync(0xffffffffu, e0, k);
            ek[1] = __shfl_sync(0xffffffffu, e1, k);
            ek[2] = __shfl_sync(0xffffffffu, e2, k);
            ek[3] = __shfl_sync(0xffffffffu, e3, k);
            sk[0] = __shfl_sync(0xffffffffu, r0, k);
            sk[1] = __shfl_sync(0xffffffffu, r1, k);
            sk[2] = __shfl_sync(0xffffffffu, r2, k);
            sk[3] = __shfl_sync(0xffffffffu, r3, k);
#pragma unroll
            for (int i = 0; i < 4; i++) {
                u64 ekk = pack2(ek[i], ek[i]);
                u64 skk = pack2(sk[i], sk[i]);
                A[i] = fma2(w0, ekk, A[i]);
                B[i] = fma2(w1, ekk, B[i]);
                C[i] = fma2(w2, skk, C[i]);
                M[i] = fma2(w3, ekk, M[i]);
                D[i] = fma2(w4, skk, D[i]);
            }
        }

#pragma unroll
        for (int i = 0; i < 4; i++) {
            int n = base + i;
            float lo, hi;
            unpack2(A[i], lo, hi);
            g_tailproj[n * 64 + lane]      = lo;
            g_tailproj[n * 64 + 32 + lane] = hi;
            unpack2(B[i], lo, hi);
            g_headrec[n * 128 + lane]      = __float2half_rn(lo);
            g_headrec[n * 128 + 32 + lane] = __float2half_rn(hi);
            unpack2(M[i], lo, hi);
            g_headrec[n * 128 + 64 + lane] = __float2half_rn(lo);
            g_headrec[n * 128 + 96 + lane] = __float2half_rn(hi);
            unpack2(C[i], lo, hi);
            g_self[n * 128 + lane]         = lo;
            g_self[n * 128 + 32 + lane]    = hi;
            unpack2(D[i], lo, hi);
            g_self[n * 128 + 64 + lane]    = lo;
            g_self[n * 128 + 96 + lane]    = hi;
        }
    }
}

// ---------------------------------------------------------------------------
// Fused CSR aggregate: one warp per node (grid-stride), 2 edges in flight per
// 16-lane group (unroll x2 => 4/warp). headrec gathers in fp16. Rel tables in
// smem. Register accumulation, direct output write (self-loop + softmax
// normalize + bias fused). Zero atomics.
__global__ void __launch_bounds__(256) aggregate_kernel(
        const float* __restrict__ attn_vec,
        const float* __restrict__ aggr_b,
        float* __restrict__ out) {
    __shared__ float4 s_rel[N_REL * 32];   // 32KB: row r = 32 float4s
    {
        const float4* src = (const float4*)g_relcat;
        for (int i = threadIdx.x; i < N_REL * 32; i += blockDim.x)
            s_rel[i] = src[i];
    }
    __syncthreads();

    int lane = threadIdx.x & 31;
    int t    = lane & 15;
    int sub  = lane >> 4;
    unsigned pmask = 3u << (lane & 30);
    int gw = blockIdx.x * (blockDim.x >> 5) + (threadIdx.x >> 5);
    int GW = gridDim.x * (blockDim.x >> 5);

    float4 v  = *(const float4*)(&attn_vec[4 * t]);
    float4 b4 = *(const float4*)(&aggr_b[4 * t]);

    for (int n = gw; n < N_ENT; n += GW) {
        int beg = g_off[n], end = g_off[n + 1];
        float4 at = *(const float4*)(&g_tailproj[n * 64 + 4 * t]);

        float ax0 = 0, ay0 = 0, az0 = 0, aw0 = 0, den0 = 0;
        float ax1 = 0, ay1 = 0, az1 = 0, aw1 = 0, den1 = 0;

#define EDGE_BODY(IDX, AX, AY, AZ, AW, DEN) do {                              \
        int x_  = g_sortkey[IDX];                                             \
        int hn_ = x_ & 0x1FFFF;                                               \
        int r_  = x_ >> 17;                                                   \
        const __half* hp_ = &g_headrec[hn_ * 128 + 4 * t];                    \
        uint2 ar_ = *(const uint2*)hp_;                                       \
        uint2 mr_ = *(const uint2*)(hp_ + 64);                                \
        float2 a01 = __half22float2(*reinterpret_cast<__half2*>(&ar_.x));     \
        float2 a23 = __half22float2(*reinterpret_cast<__half2*>(&ar_.y));     \
        float2 m01 = __half22float2(*reinterpret_cast<__half2*>(&mr_.x));     \
        float2 m23 = __half22float2(*reinterpret_cast<__half2*>(&mr_.y));     \
        float4 cr_ = s_rel[r_ * 32 + t];                                      \
        float4 mm_ = s_rel[r_ * 32 + 16 + t];                                 \
        float p0 = at.x + a01.x + cr_.x; p0 = fmaxf(p0, 0.2f * p0);           \
        float p1 = at.y + a01.y + cr_.y; p1 = fmaxf(p1, 0.2f * p1);           \
        float p2 = at.z + a23.x + cr_.z; p2 = fmaxf(p2, 0.2f * p2);           \
        float p3 = at.w + a23.y + cr_.w; p3 = fmaxf(p3, 0.2f * p3);           \
        float s_ = p0 * v.x + p1 * v.y + p2 * v.z + p3 * v.w;                 \
        s_ += __shfl_xor_sync(pmask, s_, 1);                                  \
        float ex_ = __expf(s_);                                               \
        AX = fmaf(ex_, m01.x + mm_.x, AX);                                    \
        AY = fmaf(ex_, m01.y + mm_.y, AY);                                    \
        AZ = fmaf(ex_, m23.x + mm_.z, AZ);                                    \
        AW = fmaf(ex_, m23.y + mm_.w, AW);                                    \
        DEN += ex_;                                                           \
    } while (0)

        int i = beg + sub;
        for (; i + 2 < end; i += 4) {
            EDGE_BODY(i,     ax0, ay0, az0, aw0, den0);
            EDGE_BODY(i + 2, ax1, ay1, az1, aw1, den1);
        }
        if (i < end) EDGE_BODY(i, ax0, ay0, az0, aw0, den0);
#undef EDGE_BODY

        float ax = ax0 + ax1, ay = ay0 + ay1;
        float az = az0 + az1, aw = aw0 + aw1;
        float den = den0 + den1;

        // combine the two 16-lane halves (same dims, different edges)
        ax  += __shfl_xor_sync(0xffffffffu, ax, 16);
        ay  += __shfl_xor_sync(0xffffffffu, ay, 16);
        az  += __shfl_xor_sync(0xffffffffu, az, 16);
        aw  += __shfl_xor_sync(0xffffffffu, aw, 16);
        den += __shfl_xor_sync(0xffffffffu, den, 16);

        if (sub == 0) {
            // self-loop edge + normalize + bias
            const __half* hp = &g_headrec[n * 128 + 4 * t];
            uint2 arw = *(const uint2*)hp;
            uint2 mrw = *(const uint2*)(hp + 64);
            float2 a01 = __half22float2(*reinterpret_cast<__half2*>(&arw.x));
            float2 a23 = __half22float2(*reinterpret_cast<__half2*>(&arw.y));
            float2 m01 = __half22float2(*reinterpret_cast<__half2*>(&mrw.x));
            float2 m23 = __half22float2(*reinterpret_cast<__half2*>(&mrw.y));
            float4 ars = *(const float4*)(&g_self[n * 128 + 4 * t]);
            float4 mrs = *(const float4*)(&g_self[n * 128 + 64 + 4 * t]);

            float p0 = at.x + a01.x + ars.x; p0 = fmaxf(p0, 0.2f * p0);
            float p1 = at.y + a01.y + ars.y; p1 = fmaxf(p1, 0.2f * p1);
            float p2 = at.z + a23.x + ars.z; p2 = fmaxf(p2, 0.2f * p2);
            float p3 = at.w + a23.y + ars.w; p3 = fmaxf(p3, 0.2f * p3);
            float s = p0 * v.x + p1 * v.y + p2 * v.z + p3 * v.w;
            s += __shfl_xor_sync(pmask, s, 1);
            float ex = __expf(s);

            float inv = 1.f / (den + ex + 1e-16f);
            float4 o;
            o.x = fmaf(fmaf(ex, m01.x + mrs.x, ax), inv, b4.x);
            o.y = fmaf(fmaf(ex, m01.y + mrs.y, ay), inv, b4.y);
            o.z = fmaf(fmaf(ex, m23.x + mrs.z, az), inv, b4.z);
            o.w = fmaf(fmaf(ex, m23.y + mrs.w, aw), inv, b4.w);
            *(float4*)(&out[n * 64 + 4 * t]) = o;
        }
    }
}

// ---------------------------------------------------------------------------
extern "C" void kernel_launch(void* const* d_in, const int* in_sizes, int n_in,
                              void* d_out, int out_size) {
    const float* emb_ent  = (const float*)d_in[0];
    const float* emb_rel  = (const float*)d_in[1];
    const float* attn_W   = (const float*)d_in[2];
    const float* attn_b   = (const float*)d_in[3];
    const float* attn_vec = (const float*)d_in[4];
    const float* aggr_W   = (const float*)d_in[5];
    const float* aggr_b   = (const float*)d_in[6];
    const int*   head     = (const int*)d_in[7];
    const int*   tail     = (const int*)d_in[8];
    const int*   rel      = (const int*)d_in[9];
    float*       out      = (float*)d_out;

    void* p_deg;
    cudaGetSymbolAddress(&p_deg, g_deg);
    cudaMemsetAsync(p_deg, 0, sizeof(int) * N_ENT);

    rel_tables_kernel<<<1, 64>>>(emb_rel, attn_W, attn_b, aggr_W);
    deg_kernel<<<(N_EDGE + 255) / 256, 256>>>(tail);
    scanA_kernel<<<NB_SCAN, 256>>>();
    scanB_kernel<<<1, 512>>>();
    scanC_kernel<<<NB_SCAN, 256>>>();
    scatter_kernel<<<(N_EDGE + 255) / 256, 256>>>(head, tail, rel);
    selfrel_kernel<<<(N_ENT + 7) / 8, 256>>>(emb_rel);
    node_proj_kernel<<<740, 256>>>(emb_ent, attn_W, attn_b, aggr_W);
    aggregate_kernel<<<1036, 256>>>(attn_vec, aggr_b, out);
}

// round 11
// speedup vs baseline: 1.9698x; 1.1586x over previous
#include <cuda_runtime.h>
#include <cuda_fp16.h>

#define N_ENT   100000
#define N_EDGE  1600000
#define N_REL   64
#define NB_SCAN ((N_ENT + 255) / 256)    // 391

// Scratch (allocation-free rule: __device__ globals)
static __device__ float  g_tailproj[N_ENT * 64];   // W_t · emb[n]           (fp32)
static __device__ __half g_headrec [N_ENT * 128];  // [W_h·emb | M_h·emb]    (fp16)
static __device__ float  g_relcat  [N_REL * 128];  // [W_r·emb_rel+b | M_r·emb_rel]
static __device__ int    g_deg     [N_ENT];        // in-degree (excl. self)
static __device__ int    g_off     [N_ENT + 1];    // CSR offsets
static __device__ int    g_cursor  [N_ENT];        // scatter cursors
static __device__ int    g_bsum    [NB_SCAN];      // scan block sums
static __device__ int    g_boff    [NB_SCAN];      // scan block offsets
static __device__ int    g_sortkey [N_EDGE];       // head | rel<<17, grouped by tail

typedef unsigned long long u64;

__device__ __forceinline__ u64 pack2(float lo, float hi) {
    u64 r;
    asm("mov.b64 %0, {%1, %2};" : "=l"(r) : "f"(lo), "f"(hi));
    return r;
}
__device__ __forceinline__ void unpack2(u64 v, float& lo, float& hi) {
    asm("mov.b64 {%0, %1}, %2;" : "=f"(lo), "=f"(hi) : "l"(v));
}
__device__ __forceinline__ u64 fma2(u64 a, u64 b, u64 c) {
    u64 d;
    asm("fma.rn.f32x2 %0, %1, %2, %3;" : "=l"(d) : "l"(a), "l"(b), "l"(c));
    return d;
}

// ---------------------------------------------------------------------------
// Per-relation table: relcat[r] = [W_r·emb_rel[r] + attn_b | M_r·emb_rel[r]]
__global__ void rel_tables_kernel(const float* __restrict__ emb_rel,
                                  const float* __restrict__ attn_W,
                                  const float* __restrict__ attn_b,
                                  const float* __restrict__ aggr_W) {
    int r = threadIdx.x;
    if (r >= N_REL) return;
    float ev[32];
#pragma unroll
    for (int k = 0; k < 32; k++) ev[k] = emb_rel[r * 32 + k];
    for (int o = 0; o < 64; o++) {
        float a = attn_b[o], m = 0.f;
#pragma unroll
        for (int k = 0; k < 32; k++) {
            a = fmaf(attn_W[o * 96 + 64 + k], ev[k], a);
            m = fmaf(aggr_W[o * 64 + 32 + k], ev[k], m);
        }
        g_relcat[r * 128 + o]      = a;
        g_relcat[r * 128 + 64 + o] = m;
    }
}

// ---------------------------------------------------------------------------
__global__ void deg_kernel(const int* __restrict__ tail) {
    int e = blockIdx.x * blockDim.x + threadIdx.x;
    if (e < N_EDGE) atomicAdd(&g_deg[tail[e]], 1);
}

// ---------------------------------------------------------------------------
// 3-phase multi-block exclusive scan over degrees
__global__ void scanA_kernel() {
    __shared__ int s[256];
    int n = blockIdx.x * 256 + threadIdx.x;
    s[threadIdx.x] = (n < N_ENT) ? g_deg[n] : 0;
    __syncthreads();
    for (int o = 128; o > 0; o >>= 1) {
        if (threadIdx.x < o) s[threadIdx.x] += s[threadIdx.x + o];
        __syncthreads();
    }
    if (threadIdx.x == 0) g_bsum[blockIdx.x] = s[0];
}
__global__ void scanB_kernel() {
    __shared__ int s[512];
    int tid = threadIdx.x;
    s[tid] = (tid < NB_SCAN) ? g_bsum[tid] : 0;
    __syncthreads();
    for (int d = 1; d < 512; d <<= 1) {
        int v = (tid >= d) ? s[tid - d] : 0;
        __syncthreads();
        s[tid] += v;
        __syncthreads();
    }
    if (tid < NB_SCAN) g_boff[tid] = tid ? s[tid - 1] : 0;
    if (tid == 511) g_off[N_ENT] = s[NB_SCAN - 1];
}
__global__ void scanC_kernel() {
    __shared__ int s[256];
    int n = blockIdx.x * 256 + threadIdx.x;
    int d = (n < N_ENT) ? g_deg[n] : 0;
    s[threadIdx.x] = d;
    __syncthreads();
    for (int o = 1; o < 256; o <<= 1) {
        int v = (threadIdx.x >= o) ? s[threadIdx.x - o] : 0;
        __syncthreads();
        s[threadIdx.x] += v;
        __syncthreads();
    }
    if (n < N_ENT) {
        int off = g_boff[blockIdx.x] + s[threadIdx.x] - d;   // exclusive
        g_off[n]    = off;
        g_cursor[n] = off;
    }
}

// ---------------------------------------------------------------------------
__global__ void scatter_kernel(const int* __restrict__ head,
                               const int* __restrict__ tail,
                               const int* __restrict__ rel) {
    int e = blockIdx.x * blockDim.x + threadIdx.x;
    if (e >= N_EDGE) return;
    int pos = atomicAdd(&g_cursor[tail[e]], 1);
    g_sortkey[pos] = head[e] | (rel[e] << 17);
}

// ---------------------------------------------------------------------------
// Per-node projections (3 GEMVs fused): 4 nodes per warp per k-step, weights
// packed as (o=lane, o=lane+32) float2 pairs -> LDS.64 + fma.rn.f32x2.
// headrec written fp16. (The self-record projections are gone: the aggregate
// kernel synthesizes them as the mean of relcat rows over incoming edges.)
__global__ void __launch_bounds__(256) node_proj_kernel(
        const float* __restrict__ emb_ent,
        const float* __restrict__ attn_W,
        const float* __restrict__ aggr_W) {
    __shared__ float2 s_w[3][32 * 32];   // 24KB
    for (int i = threadIdx.x; i < 1024; i += blockDim.x) {
        int k = i >> 5, l = i & 31;
        s_w[0][i] = make_float2(attn_W[l * 96 + k],      attn_W[(l + 32) * 96 + k]);
        s_w[1][i] = make_float2(attn_W[l * 96 + 32 + k], attn_W[(l + 32) * 96 + 32 + k]);
        s_w[2][i] = make_float2(aggr_W[l * 64 + k],      aggr_W[(l + 32) * 64 + k]);
    }
    __syncthreads();

    int lane = threadIdx.x & 31;
    int gw   = blockIdx.x * (blockDim.x >> 5) + (threadIdx.x >> 5);
    int GW   = gridDim.x * (blockDim.x >> 5);

    for (int base = gw * 4; base < N_ENT; base += GW * 4) {   // N_ENT % 4 == 0
        float e0 = emb_ent[(base + 0) * 32 + lane];
        float e1 = emb_ent[(base + 1) * 32 + lane];
        float e2 = emb_ent[(base + 2) * 32 + lane];
        float e3 = emb_ent[(base + 3) * 32 + lane];

        u64 A[4], B[4], M[4];
#pragma unroll
        for (int i = 0; i < 4; i++) { A[i] = 0; B[i] = 0; M[i] = 0; }

#pragma unroll
        for (int k = 0; k < 32; k++) {
            u64 w0 = *(const u64*)&s_w[0][k * 32 + lane];
            u64 w1 = *(const u64*)&s_w[1][k * 32 + lane];
            u64 w2 = *(const u64*)&s_w[2][k * 32 + lane];
            float ek[4];
            ek[0] = __shfl_sync(0xffffffffu, e0, k);
            ek[1] = __shfl_sync(0xffffffffu, e1, k);
            ek[2] = __shfl_sync(0xffffffffu, e2, k);
            ek[3] = __shfl_sync(0xffffffffu, e3, k);
#pragma unroll
            for (int i = 0; i < 4; i++) {
                u64 ekk = pack2(ek[i], ek[i]);
                A[i] = fma2(w0, ekk, A[i]);
                B[i] = fma2(w1, ekk, B[i]);
                M[i] = fma2(w2, ekk, M[i]);
            }
        }

#pragma unroll
        for (int i = 0; i < 4; i++) {
            int n = base + i;
            float lo, hi;
            unpack2(A[i], lo, hi);
            g_tailproj[n * 64 + lane]      = lo;
            g_tailproj[n * 64 + 32 + lane] = hi;
            unpack2(B[i], lo, hi);
            g_headrec[n * 128 + lane]      = __float2half_rn(lo);
            g_headrec[n * 128 + 32 + lane] = __float2half_rn(hi);
            unpack2(M[i], lo, hi);
            g_headrec[n * 128 + 64 + lane] = __float2half_rn(lo);
            g_headrec[n * 128 + 96 + lane] = __float2half_rn(hi);
        }
    }
}

// ---------------------------------------------------------------------------
// Fused CSR aggregate: one warp per node (grid-stride), 2 edges in flight per
// 16-lane group (unroll x2 => 4/warp). headrec gathers fp16, rel tables in
// smem. Also accumulates sum(relcat[r]) across the run: its mean IS the
// self-loop record (mean is affine-compatible with W_r·(.)+b). Direct output
// write (self-loop + softmax normalize + bias fused). Zero atomics.
__global__ void __launch_bounds__(256) aggregate_kernel(
        const float* __restrict__ attn_vec,
        const float* __restrict__ aggr_b,
        float* __restrict__ out) {
    __shared__ float4 s_rel[N_REL * 32];   // 32KB: row r = 32 float4s
    {
        const float4* src = (const float4*)g_relcat;
        for (int i = threadIdx.x; i < N_REL * 32; i += blockDim.x)
            s_rel[i] = src[i];
    }
    __syncthreads();

    int lane = threadIdx.x & 31;
    int t    = lane & 15;
    int sub  = lane >> 4;
    unsigned pmask = 3u << (lane & 30);
    int gw = blockIdx.x * (blockDim.x >> 5) + (threadIdx.x >> 5);
    int GW = gridDim.x * (blockDim.x >> 5);

    float4 v  = *(const float4*)(&attn_vec[4 * t]);
    float4 b4 = *(const float4*)(&aggr_b[4 * t]);

    for (int n = gw; n < N_ENT; n += GW) {
        int beg = g_off[n], end = g_off[n + 1];
        float4 at = *(const float4*)(&g_tailproj[n * 64 + 4 * t]);

        float ax0 = 0, ay0 = 0, az0 = 0, aw0 = 0, den0 = 0;
        float ax1 = 0, ay1 = 0, az1 = 0, aw1 = 0, den1 = 0;
        float4 scr = make_float4(0.f, 0.f, 0.f, 0.f);   // sum of attn relcat rows
        float4 smm = make_float4(0.f, 0.f, 0.f, 0.f);   // sum of msg relcat rows

#define EDGE_BODY(IDX, AX, AY, AZ, AW, DEN) do {                              \
        int x_  = g_sortkey[IDX];                                             \
        int hn_ = x_ & 0x1FFFF;                                               \
        int r_  = x_ >> 17;                                                   \
        const __half* hp_ = &g_headrec[hn_ * 128 + 4 * t];                    \
        uint2 ar_ = *(const uint2*)hp_;                                       \
        uint2 mr_ = *(const uint2*)(hp_ + 64);                                \
        float2 a01 = __half22float2(*reinterpret_cast<__half2*>(&ar_.x));     \
        float2 a23 = __half22float2(*reinterpret_cast<__half2*>(&ar_.y));     \
        float2 m01 = __half22float2(*reinterpret_cast<__half2*>(&mr_.x));     \
        float2 m23 = __half22float2(*reinterpret_cast<__half2*>(&mr_.y));     \
        float4 cr_ = s_rel[r_ * 32 + t];                                      \
        float4 mm_ = s_rel[r_ * 32 + 16 + t];                                 \
        scr.x += cr_.x; scr.y += cr_.y; scr.z += cr_.z; scr.w += cr_.w;       \
        smm.x += mm_.x; smm.y += mm_.y; smm.z += mm_.z; smm.w += mm_.w;       \
        float p0 = at.x + a01.x + cr_.x; p0 = fmaxf(p0, 0.2f * p0);           \
        float p1 = at.y + a01.y + cr_.y; p1 = fmaxf(p1, 0.2f * p1);           \
        float p2 = at.z + a23.x + cr_.z; p2 = fmaxf(p2, 0.2f * p2);           \
        float p3 = at.w + a23.y + cr_.w; p3 = fmaxf(p3, 0.2f * p3);           \
        float s_ = p0 * v.x + p1 * v.y + p2 * v.z + p3 * v.w;                 \
        s_ += __shfl_xor_sync(pmask, s_, 1);                                  \
        float ex_ = __expf(s_);                                               \
        AX = fmaf(ex_, m01.x + mm_.x, AX);                                    \
        AY = fmaf(ex_, m01.y + mm_.y, AY);                                    \
        AZ = fmaf(ex_, m23.x + mm_.z, AZ);                                    \
        AW = fmaf(ex_, m23.y + mm_.w, AW);                                    \
        DEN += ex_;                                                           \
    } while (0)

        int i = beg + sub;
        for (; i + 2 < end; i += 4) {
            EDGE_BODY(i,     ax0, ay0, az0, aw0, den0);
            EDGE_BODY(i + 2, ax1, ay1, az1, aw1, den1);
        }
        if (i < end) EDGE_BODY(i, ax0, ay0, az0, aw0, den0);
#undef EDGE_BODY

        float ax = ax0 + ax1, ay = ay0 + ay1;
        float az = az0 + az1, aw = aw0 + aw1;
        float den = den0 + den1;

        // combine the two 16-lane halves (same dims, different edges)
        ax  += __shfl_xor_sync(0xffffffffu, ax, 16);
        ay  += __shfl_xor_sync(0xffffffffu, ay, 16);
        az  += __shfl_xor_sync(0xffffffffu, az, 16);
        aw  += __shfl_xor_sync(0xffffffffu, aw, 16);
        den += __shfl_xor_sync(0xffffffffu, den, 16);
        scr.x += __shfl_xor_sync(0xffffffffu, scr.x, 16);
        scr.y += __shfl_xor_sync(0xffffffffu, scr.y, 16);
        scr.z += __shfl_xor_sync(0xffffffffu, scr.z, 16);
        scr.w += __shfl_xor_sync(0xffffffffu, scr.w, 16);
        smm.x += __shfl_xor_sync(0xffffffffu, smm.x, 16);
        smm.y += __shfl_xor_sync(0xffffffffu, smm.y, 16);
        smm.z += __shfl_xor_sync(0xffffffffu, smm.z, 16);
        smm.w += __shfl_xor_sync(0xffffffffu, smm.w, 16);

        if (sub == 0) {
            // self record = mean of relcat rows over incoming edges
            float invd = 1.f / (float)(end - beg);
            // self-loop edge + normalize + bias
            const __half* hp = &g_headrec[n * 128 + 4 * t];
            uint2 arw = *(const uint2*)hp;
            uint2 mrw = *(const uint2*)(hp + 64);
            float2 a01 = __half22float2(*reinterpret_cast<__half2*>(&arw.x));
            float2 a23 = __half22float2(*reinterpret_cast<__half2*>(&arw.y));
            float2 m01 = __half22float2(*reinterpret_cast<__half2*>(&mrw.x));
            float2 m23 = __half22float2(*reinterpret_cast<__half2*>(&mrw.y));

            float p0 = at.x + a01.x + scr.x * invd; p0 = fmaxf(p0, 0.2f * p0);
            float p1 = at.y + a01.y + scr.y * invd; p1 = fmaxf(p1, 0.2f * p1);
            float p2 = at.z + a23.x + scr.z * invd; p2 = fmaxf(p2, 0.2f * p2);
            float p3 = at.w + a23.y + scr.w * invd; p3 = fmaxf(p3, 0.2f * p3);
            float s = p0 * v.x + p1 * v.y + p2 * v.z + p3 * v.w;
            s += __shfl_xor_sync(pmask, s, 1);
            float ex = __expf(s);

            float inv = 1.f / (den + ex + 1e-16f);
            float4 o;
            o.x = fmaf(fmaf(ex, m01.x + smm.x * invd, ax), inv, b4.x);
            o.y = fmaf(fmaf(ex, m01.y + smm.y * invd, ay), inv, b4.y);
            o.z = fmaf(fmaf(ex, m23.x + smm.z * invd, az), inv, b4.z);
            o.w = fmaf(fmaf(ex, m23.y + smm.w * invd, aw), inv, b4.w);
            *(float4*)(&out[n * 64 + 4 * t]) = o;
        }
    }
}

// ---------------------------------------------------------------------------
extern "C" void kernel_launch(void* const* d_in, const int* in_sizes, int n_in,
                              void* d_out, int out_size) {
    const float* emb_ent  = (const float*)d_in[0];
    const float* emb_rel  = (const float*)d_in[1];
    const float* attn_W   = (const float*)d_in[2];
    const float* attn_b   = (const float*)d_in[3];
    const float* attn_vec = (const float*)d_in[4];
    const float* aggr_W   = (const float*)d_in[5];
    const float* aggr_b   = (const float*)d_in[6];
    const int*   head     = (const int*)d_in[7];
    const int*   tail     = (const int*)d_in[8];
    const int*   rel      = (const int*)d_in[9];
    float*       out      = (float*)d_out;

    void* p_deg;
    cudaGetSymbolAddress(&p_deg, g_deg);
    cudaMemsetAsync(p_deg, 0, sizeof(int) * N_ENT);

    rel_tables_kernel<<<1, 64>>>(emb_rel, attn_W, attn_b, aggr_W);
    deg_kernel<<<(N_EDGE + 255) / 256, 256>>>(tail);
    scanA_kernel<<<NB_SCAN, 256>>>();
    scanB_kernel<<<1, 512>>>();
    scanC_kernel<<<NB_SCAN, 256>>>();
    scatter_kernel<<<(N_EDGE + 255) / 256, 256>>>(head, tail, rel);
    node_proj_kernel<<<740, 256>>>(emb_ent, attn_W, aggr_W);
    aggregate_kernel<<<1036, 256>>>(attn_vec, aggr_b, out);
}